// round 3
// baseline (speedup 1.0000x reference)
#include <cuda_runtime.h>

// ---------------------------------------------------------------------------
// StridedwindowAttention  (B=4, C=256, H=W=64, STRIDE=4, NH=8, DH=32)
//
// Stage 1 (proj_kernel): 1x1-conv projections q/k/v as GEMMs, written into
//   windowed layout  g_*[(((b*16+sy*4+sx)*8+head)*256+l)*32+dh].
// Stage 2 (attn_kernel): one block per (b,window,head); thread i owns query
//   row i; K/V in smem; uniform masked-key skip; shift-free softmax.
//
// Both hot loops use packed fp32 FMA (PTX fma.rn.f32x2 -> SASS FFMA2):
// 2 IEEE fp32 FMAs per instruction, numerically identical to scalar FFMA.
// ---------------------------------------------------------------------------

#define NH   8
#define DH   32
#define LTOK 256
#define HW   4096
#define CIN  256
#define WBUF_SZ (4 * 16 * NH * LTOK * DH)   // 4,194,304 floats = 16 MB

__device__ float g_q[WBUF_SZ];
__device__ float g_k[WBUF_SZ];
__device__ float g_v[WBUF_SZ];

typedef unsigned long long ull;

__device__ __forceinline__ ull fma2(ull a, ull b, ull c) {
    ull d;
    asm("fma.rn.f32x2 %0, %1, %2, %3;" : "=l"(d) : "l"(a), "l"(b), "l"(c));
    return d;
}
__device__ __forceinline__ ull mul2(ull a, ull b) {
    ull d;
    asm("mul.rn.f32x2 %0, %1, %2;" : "=l"(d) : "l"(a), "l"(b));
    return d;
}
__device__ __forceinline__ ull pack2(float lo, float hi) {
    ull d;
    unsigned int l = __float_as_uint(lo), h = __float_as_uint(hi);
    asm("mov.b64 %0, {%1, %2};" : "=l"(d) : "r"(l), "r"(h));
    return d;
}
__device__ __forceinline__ float2 unpack2(ull v) {
    unsigned int l, h;
    asm("mov.b64 {%0, %1}, %2;" : "=r"(l), "=r"(h) : "l"(v));
    return make_float2(__uint_as_float(l), __uint_as_float(h));
}

// ---------------------------------------------------------------------------
// Projection GEMM: grid (64, 4, 12), block 256.
//   blockIdx.x = h (one image row = 64 pixels), blockIdx.y = o-tile,
//   blockIdx.z = proj*4 + batch.
// Thread micro-tile: rows o0 + tm + {0,16,32,48},
//                    cols p0 + {2tn, 2tn+1, 2tn+32, 2tn+33}.
// As2 holds each weight duplicated so the broadcast operand is one LDS.64.
// ---------------------------------------------------------------------------
__global__ __launch_bounds__(256) void proj_kernel(
    const float* __restrict__ fq, const float* __restrict__ fk,
    const float* __restrict__ fv,
    const float* __restrict__ qw, const float* __restrict__ qb,
    const float* __restrict__ kw, const float* __restrict__ kb,
    const float* __restrict__ vw, const float* __restrict__ vb)
{
    const int z    = blockIdx.z;
    const int proj = z >> 2;
    const int b    = z & 3;

    const float* X;  const float* Wm; const float* bias; float* Out;
    if (proj == 0)      { X = fq; Wm = qw; bias = qb; Out = g_q; }
    else if (proj == 1) { X = fk; Wm = kw; bias = kb; Out = g_k; }
    else                { X = fv; Wm = vw; bias = vb; Out = g_v; }
    X += (size_t)b * CIN * HW;

    const int p0 = blockIdx.x * 64;   // pixel base (h = blockIdx.x)
    const int o0 = blockIdx.y * 64;   // out-channel base
    const int t  = threadIdx.x;
    const int tm = t >> 4;            // 0..15
    const int tn = t & 15;            // 0..15

    __shared__ float As2[16][128];    // [kk][2*o_local] duplicated pairs
    __shared__ float Bs[16][64];      // [kk][p_local]
    __shared__ float Cs[64][65];      // staging for coalesced windowed stores

    ull acc2[4][2];
    #pragma unroll
    for (int i = 0; i < 4; i++) { acc2[i][0] = 0ull; acc2[i][1] = 0ull; }

    const int ar  = t >> 2;           // 0..63 (A row)
    const int aq4 = t & 3;            // k-quad
    const int bkk = t >> 4;           // 0..15 (B k)
    const int bc4 = t & 15;           // B col quad

    for (int k0 = 0; k0 < CIN; k0 += 16) {
        if (k0) __syncthreads();
        // A tile: 64 o x 16 k, duplicated (w,w) pairs, k-major
        {
            float4 wv = *(const float4*)&Wm[(size_t)(o0 + ar) * CIN + k0 + aq4 * 4];
            *(float2*)&As2[aq4 * 4 + 0][2 * ar] = make_float2(wv.x, wv.x);
            *(float2*)&As2[aq4 * 4 + 1][2 * ar] = make_float2(wv.y, wv.y);
            *(float2*)&As2[aq4 * 4 + 2][2 * ar] = make_float2(wv.z, wv.z);
            *(float2*)&As2[aq4 * 4 + 3][2 * ar] = make_float2(wv.w, wv.w);
        }
        // B tile: 16 k x 64 p
        {
            float4 xv = *(const float4*)&X[(size_t)(k0 + bkk) * HW + p0 + bc4 * 4];
            *(float4*)&Bs[bkk][bc4 * 4] = xv;
        }
        __syncthreads();

        #pragma unroll
        for (int kk = 0; kk < 16; kk++) {
            const ull a0 = *(const ull*)&As2[kk][2 * tm];
            const ull a1 = *(const ull*)&As2[kk][2 * (tm + 16)];
            const ull a2 = *(const ull*)&As2[kk][2 * (tm + 32)];
            const ull a3 = *(const ull*)&As2[kk][2 * (tm + 48)];
            const ull b01 = *(const ull*)&Bs[kk][2 * tn];
            const ull b23 = *(const ull*)&Bs[kk][2 * tn + 32];
            acc2[0][0] = fma2(a0, b01, acc2[0][0]);
            acc2[0][1] = fma2(a0, b23, acc2[0][1]);
            acc2[1][0] = fma2(a1, b01, acc2[1][0]);
            acc2[1][1] = fma2(a1, b23, acc2[1][1]);
            acc2[2][0] = fma2(a2, b01, acc2[2][0]);
            acc2[2][1] = fma2(a2, b23, acc2[2][1]);
            acc2[3][0] = fma2(a3, b01, acc2[3][0]);
            acc2[3][1] = fma2(a3, b23, acc2[3][1]);
        }
    }

    // stage C tile into smem so windowed-layout stores can be float4
    __syncthreads();
    #pragma unroll
    for (int i = 0; i < 4; i++) {
        const int r = tm + 16 * i;
        float2 c01 = unpack2(acc2[i][0]);
        float2 c23 = unpack2(acc2[i][1]);
        Cs[r][2 * tn + 0]  = c01.x;
        Cs[r][2 * tn + 1]  = c01.y;
        Cs[r][2 * tn + 32] = c23.x;
        Cs[r][2 * tn + 33] = c23.y;
    }
    __syncthreads();

    const int h  = blockIdx.x;
    const int sy = h & 3;
    const int hb = h >> 2;

    #pragma unroll
    for (int it = 0; it < 4; it++) {
        const int id = it * 256 + t;  // 0..1023
        const int o4 = id >> 6;       // 0..15
        const int p  = id & 63;       // local pixel = w
        const int o  = o0 + o4 * 4;
        const int head = o >> 5;
        const int dh   = o & 31;
        const int sx = p & 3;
        const int wb = p >> 2;
        const int l  = hb * 16 + wb;

        float4 v;
        v.x = Cs[o4 * 4 + 0][p] + bias[o + 0];
        v.y = Cs[o4 * 4 + 1][p] + bias[o + 1];
        v.z = Cs[o4 * 4 + 2][p] + bias[o + 2];
        v.w = Cs[o4 * 4 + 3][p] + bias[o + 3];

        const size_t idx =
            ((((size_t)(b * 16 + sy * 4 + sx) * NH + head) * LTOK) + l) * DH + dh;
        *(float4*)&Out[idx] = v;
    }
}

// ---------------------------------------------------------------------------
// Attention: grid (8 heads, 16 windows, 4 batch), block 256, 66.56 KB dyn smem
// ---------------------------------------------------------------------------
__global__ __launch_bounds__(256) void attn_kernel(
    const float* __restrict__ mask_q, const float* __restrict__ mask_k,
    float* __restrict__ out)
{
    extern __shared__ float sm[];
    float* Ks  = sm;                  // 256*32
    float* Vs  = sm + LTOK * DH;      // 256*32
    float* mks = sm + 2 * LTOK * DH;  // 256

    const int head = blockIdx.x;
    const int win  = blockIdx.y;      // sy*4 + sx
    const int b    = blockIdx.z;
    const int sy   = win >> 2;
    const int sx   = win & 3;
    const int i    = threadIdx.x;     // query row l

    const size_t base = (((size_t)(b * 16 + win) * NH) + head) * (LTOK * DH);

    // cooperative K/V tile loads (fully coalesced float4)
    {
        const float4* kg = (const float4*)(g_k + base);
        const float4* vg = (const float4*)(g_v + base);
        float4* ks4 = (float4*)Ks;
        float4* vs4 = (float4*)Vs;
        #pragma unroll
        for (int u = 0; u < 8; u++) {
            ks4[u * 256 + i] = kg[u * 256 + i];
            vs4[u * 256 + i] = vg[u * 256 + i];
        }
    }

    // windowed mask gather: token j -> pixel (hb*4+sy, wb*4+sx)
    const int hb = i >> 4, wb = i & 15;
    const int h  = hb * 4 + sy;
    const int w  = wb * 4 + sx;
    const float my_mk = __ldg(&mask_k[(size_t)b * HW + h * 64 + w]);
    const float my_mq = __ldg(&mask_q[(size_t)b * HW + h * 64 + w]);
    mks[i] = my_mk;

    // barrier doubles as reduction: count of unmasked keys
    const int kcnt = __syncthreads_count(my_mk != 0.0f);

    // Q row -> packed pairs, pre-scaled by head_dim^-0.5
    const float scaling = 0.17677669529663687f;  // 32^-0.5
    ull q2[DH / 2];
    {
        const ull sc2 = pack2(scaling, scaling);
        const ulonglong2* qg = (const ulonglong2*)(g_q + base + (size_t)i * DH);
        #pragma unroll
        for (int u = 0; u < 8; u++) {
            ulonglong2 qq = qg[u];
            q2[2 * u + 0] = mul2(qq.x, sc2);
            q2[2 * u + 1] = mul2(qq.y, sc2);
        }
    }

    ull o2[DH / 2];
    #pragma unroll
    for (int d = 0; d < DH / 2; d++) o2[d] = 0ull;
    float denom = 0.0f;

    for (int j = 0; j < LTOK; j++) {
        if (mks[j] == 0.0f) continue;   // uniform across block: no divergence

        // QK dot product: packed pairs, halves summed at the end
        const ulonglong2* kj = (const ulonglong2*)(Ks + j * DH);
        ull s2 = 0ull;
        #pragma unroll
        for (int u = 0; u < 8; u++) {
            ulonglong2 kv = kj[u];
            s2 = fma2(q2[2 * u + 0], kv.x, s2);
            s2 = fma2(q2[2 * u + 1], kv.y, s2);
        }
        float2 sh = unpack2(s2);
        const float p = __expf(sh.x + sh.y);
        denom += p;

        const ull p2 = pack2(p, p);
        const ulonglong2* vj = (const ulonglong2*)(Vs + j * DH);
        #pragma unroll
        for (int u = 0; u < 8; u++) {
            ulonglong2 vv = vj[u];
            o2[2 * u + 0] = fma2(p2, vv.x, o2[2 * u + 0]);
            o2[2 * u + 1] = fma2(p2, vv.y, o2[2 * u + 1]);
        }
    }

    const bool kept = (my_mq != 0.0f) && (kcnt > 0);
    const float inv = kept ? (1.0f / denom) : 0.0f;

    // de-window store: out[b, head*32+dh, h, w]
    float* op = out + ((size_t)b * 256 + head * 32) * HW + (size_t)h * 64 + w;
    #pragma unroll
    for (int d = 0; d < DH / 2; d++) {
        float2 ov = unpack2(o2[d]);
        op[(size_t)(2 * d + 0) * HW] = ov.x * inv;
        op[(size_t)(2 * d + 1) * HW] = ov.y * inv;
    }
}

// ---------------------------------------------------------------------------
extern "C" void kernel_launch(void* const* d_in, const int* in_sizes, int n_in,
                              void* d_out, int out_size)
{
    const float* fq     = (const float*)d_in[0];
    const float* fk     = (const float*)d_in[1];
    const float* fv     = (const float*)d_in[2];
    const float* mask_q = (const float*)d_in[3];
    const float* mask_k = (const float*)d_in[4];
    const float* qw     = (const float*)d_in[5];
    const float* qb     = (const float*)d_in[6];
    const float* kw     = (const float*)d_in[7];
    const float* kb     = (const float*)d_in[8];
    const float* vw     = (const float*)d_in[9];
    const float* vb     = (const float*)d_in[10];
    float* out = (float*)d_out;

    proj_kernel<<<dim3(64, 4, 12), 256>>>(fq, fk, fv, qw, qb, kw, kb, vw, vb);

    const int attn_smem = (2 * LTOK * DH + LTOK) * (int)sizeof(float);  // 66560
    cudaFuncSetAttribute(attn_kernel,
                         cudaFuncAttributeMaxDynamicSharedMemorySize, attn_smem);
    attn_kernel<<<dim3(NH, 16, 4), 256, attn_smem>>>(mask_q, mask_k, out);
}

// round 5
// speedup vs baseline: 1.1800x; 1.1800x over previous
#include <cuda_runtime.h>

// ---------------------------------------------------------------------------
// StridedwindowAttention  (B=4, C=256, H=W=64, STRIDE=4, NH=8, DH=32)
//
// Stage 1 (proj_kernel): q/k/v 1x1-conv projections as GEMMs -> windowed
//   layout  g_*[(((b*16+sy*4+sx)*8+head)*256+l)*32+dh].
//   128(o) x 64(px) block tile, k-tile 16, DOUBLE-BUFFERED smem, 8x4
//   micro-tile, FFMA2 throughout.
// Stage 2 (attn_kernel): one block per (b,window,head); 128 threads, each
//   owns query rows i and i+128 (K/V smem reads amortized 2x). Uniform
//   masked-key skip; shift-free softmax; 4-way split QK chains for ILP.
// ---------------------------------------------------------------------------

#define NH   8
#define DH   32
#define LTOK 256
#define HW   4096
#define CIN  256
#define WBUF_SZ (4 * 16 * NH * LTOK * DH)   // 16 MB each

__device__ float g_q[WBUF_SZ];
__device__ float g_k[WBUF_SZ];
__device__ float g_v[WBUF_SZ];

typedef unsigned long long ull;

__device__ __forceinline__ ull fma2(ull a, ull b, ull c) {
    ull d;
    asm("fma.rn.f32x2 %0, %1, %2, %3;" : "=l"(d) : "l"(a), "l"(b), "l"(c));
    return d;
}
__device__ __forceinline__ ull mul2(ull a, ull b) {
    ull d;
    asm("mul.rn.f32x2 %0, %1, %2;" : "=l"(d) : "l"(a), "l"(b));
    return d;
}
__device__ __forceinline__ ull pack2(float lo, float hi) {
    ull d;
    unsigned int l = __float_as_uint(lo), h = __float_as_uint(hi);
    asm("mov.b64 %0, {%1, %2};" : "=l"(d) : "r"(l), "r"(h));
    return d;
}
__device__ __forceinline__ float2 unpack2(ull v) {
    unsigned int l, h;
    asm("mov.b64 {%0, %1}, %2;" : "=r"(l), "=r"(h) : "l"(v));
    return make_float2(__uint_as_float(l), __uint_as_float(h));
}

// ---------------------------------------------------------------------------
// Projection GEMM: grid (64, 2, 12), block 256, 40 KB dynamic smem.
//   blockIdx.x = h (image row = 64 px), blockIdx.y = o-tile (128 ch),
//   blockIdx.z = proj*4 + batch.
// Thread micro-tile: rows o0 + tm + 16*{0..7}, cols p0 + 4*tn + {0..3}.
// As2 holds duplicated (w,w) pairs so the broadcast operand is one LDS.64;
// B row of 4 cols is one LDS.128 (= ulonglong2).
// ---------------------------------------------------------------------------
__global__ __launch_bounds__(256) void proj_kernel(
    const float* __restrict__ fq, const float* __restrict__ fk,
    const float* __restrict__ fv,
    const float* __restrict__ qw, const float* __restrict__ qb,
    const float* __restrict__ kw, const float* __restrict__ kb,
    const float* __restrict__ vw, const float* __restrict__ vb)
{
    extern __shared__ float smp[];
    float* As2 = smp;                 // [2][16][256] duplicated pairs (32 KB)
    float* BsS = smp + 2 * 16 * 256;  // [2][16][64]                  (8 KB)
    float* Cs  = smp;                 // [128][68] (reused, 34.8 KB)

    const int z    = blockIdx.z;
    const int proj = z >> 2;
    const int b    = z & 3;

    const float* X;  const float* Wm; const float* bias; float* Out;
    if (proj == 0)      { X = fq; Wm = qw; bias = qb; Out = g_q; }
    else if (proj == 1) { X = fk; Wm = kw; bias = kb; Out = g_k; }
    else                { X = fv; Wm = vw; bias = vb; Out = g_v; }
    X += (size_t)b * CIN * HW;

    const int p0 = blockIdx.x * 64;   // pixel base (h = blockIdx.x)
    const int o0 = blockIdx.y * 128;  // out-channel base
    const int t  = threadIdx.x;
    const int tm = t >> 4;            // 0..15
    const int tn = t & 15;            // 0..15

    // loader indices
    const int ar = t >> 1;            // 0..127  A row
    const int ah = t & 1;             // k-half (8 k's each)
    const int bkk = t >> 4;           // 0..15   B k row
    const int bc4 = t & 15;           // B col quad

    ull acc[8][2];
    #pragma unroll
    for (int i = 0; i < 8; i++) { acc[i][0] = 0ull; acc[i][1] = 0ull; }

    float4 wa0, wa1, xb;

    // ---- prologue: load tile 0 ----
    {
        const float* wp = &Wm[(size_t)(o0 + ar) * CIN + ah * 8];
        wa0 = *(const float4*)wp;
        wa1 = *(const float4*)(wp + 4);
        xb  = *(const float4*)&X[(size_t)bkk * HW + p0 + bc4 * 4];
    }
    {
        float* a = As2;               // stage 0
        const int kb8 = ah * 8;
        const int col = 2 * ar;
        *(float2*)&a[(kb8 + 0) * 256 + col] = make_float2(wa0.x, wa0.x);
        *(float2*)&a[(kb8 + 1) * 256 + col] = make_float2(wa0.y, wa0.y);
        *(float2*)&a[(kb8 + 2) * 256 + col] = make_float2(wa0.z, wa0.z);
        *(float2*)&a[(kb8 + 3) * 256 + col] = make_float2(wa0.w, wa0.w);
        *(float2*)&a[(kb8 + 4) * 256 + col] = make_float2(wa1.x, wa1.x);
        *(float2*)&a[(kb8 + 5) * 256 + col] = make_float2(wa1.y, wa1.y);
        *(float2*)&a[(kb8 + 6) * 256 + col] = make_float2(wa1.z, wa1.z);
        *(float2*)&a[(kb8 + 7) * 256 + col] = make_float2(wa1.w, wa1.w);
        *(float4*)&BsS[bkk * 64 + bc4 * 4] = xb;
    }
    __syncthreads();

    #pragma unroll 1
    for (int kt = 0; kt < 16; kt++) {
        const int s = kt & 1;
        // prefetch next tile (hidden under compute)
        if (kt < 15) {
            const int k0n = (kt + 1) * 16;
            const float* wp = &Wm[(size_t)(o0 + ar) * CIN + k0n + ah * 8];
            wa0 = *(const float4*)wp;
            wa1 = *(const float4*)(wp + 4);
            xb  = *(const float4*)&X[(size_t)(k0n + bkk) * HW + p0 + bc4 * 4];
        }
        // compute on stage s
        const float* a  = As2 + s * (16 * 256);
        const float* bs = BsS + s * (16 * 64);
        #pragma unroll
        for (int kk = 0; kk < 16; kk++) {
            const ulonglong2 bv = *(const ulonglong2*)&bs[kk * 64 + 4 * tn];
            #pragma unroll
            for (int i = 0; i < 8; i++) {
                const ull av = *(const ull*)&a[kk * 256 + 2 * (tm + 16 * i)];
                acc[i][0] = fma2(av, bv.x, acc[i][0]);
                acc[i][1] = fma2(av, bv.y, acc[i][1]);
            }
        }
        // store next tile into the other stage
        if (kt < 15) {
            float* an = As2 + (s ^ 1) * (16 * 256);
            const int kb8 = ah * 8;
            const int col = 2 * ar;
            *(float2*)&an[(kb8 + 0) * 256 + col] = make_float2(wa0.x, wa0.x);
            *(float2*)&an[(kb8 + 1) * 256 + col] = make_float2(wa0.y, wa0.y);
            *(float2*)&an[(kb8 + 2) * 256 + col] = make_float2(wa0.z, wa0.z);
            *(float2*)&an[(kb8 + 3) * 256 + col] = make_float2(wa0.w, wa0.w);
            *(float2*)&an[(kb8 + 4) * 256 + col] = make_float2(wa1.x, wa1.x);
            *(float2*)&an[(kb8 + 5) * 256 + col] = make_float2(wa1.y, wa1.y);
            *(float2*)&an[(kb8 + 6) * 256 + col] = make_float2(wa1.z, wa1.z);
            *(float2*)&an[(kb8 + 7) * 256 + col] = make_float2(wa1.w, wa1.w);
            *(float4*)&BsS[(s ^ 1) * (16 * 64) + bkk * 64 + bc4 * 4] = xb;
        }
        __syncthreads();   // final iteration: also guards Cs reuse below
    }

    // ---- stage C tile (128 x 64) into smem, stride 68 ----
    #pragma unroll
    for (int i = 0; i < 8; i++) {
        const float2 c0 = unpack2(acc[i][0]);
        const float2 c1 = unpack2(acc[i][1]);
        float* c = &Cs[(tm + 16 * i) * 68 + 4 * tn];
        float4 v = make_float4(c0.x, c0.y, c1.x, c1.y);
        *(float4*)c = v;
    }
    __syncthreads();

    // ---- windowed stores: 128 ch x 64 px, float4 over dh ----
    const int h  = blockIdx.x;
    const int sy = h & 3;
    const int hb = h >> 2;

    #pragma unroll
    for (int it = 0; it < 8; it++) {
        const int id = it * 256 + t;  // 0..2047
        const int o4 = id >> 6;       // 0..31
        const int p  = id & 63;       // local pixel = w
        const int o  = o0 + o4 * 4;
        const int head = o >> 5;
        const int dh   = o & 31;
        const int sx = p & 3;
        const int wb = p >> 2;
        const int l  = hb * 16 + wb;

        float4 v;
        v.x = Cs[(o4 * 4 + 0) * 68 + p] + bias[o + 0];
        v.y = Cs[(o4 * 4 + 1) * 68 + p] + bias[o + 1];
        v.z = Cs[(o4 * 4 + 2) * 68 + p] + bias[o + 2];
        v.w = Cs[(o4 * 4 + 3) * 68 + p] + bias[o + 3];

        const size_t idx =
            ((((size_t)(b * 16 + sy * 4 + sx) * NH + head) * LTOK) + l) * DH + dh;
        *(float4*)&Out[idx] = v;
    }
}

// ---------------------------------------------------------------------------
// Attention: grid (8 heads, 16 windows, 4 batch), block 128, 66.56 KB smem.
// Thread i owns query rows i and i+128 -> K/V smem reads amortized 2x.
// ---------------------------------------------------------------------------
__global__ __launch_bounds__(128) void attn_kernel(
    const float* __restrict__ mask_q, const float* __restrict__ mask_k,
    float* __restrict__ out)
{
    extern __shared__ float sm[];
    float* Ks  = sm;                  // 256*32
    float* Vs  = sm + LTOK * DH;      // 256*32
    float* mks = sm + 2 * LTOK * DH;  // 256

    const int head = blockIdx.x;
    const int win  = blockIdx.y;      // sy*4 + sx
    const int b    = blockIdx.z;
    const int sy   = win >> 2;
    const int sx   = win & 3;
    const int i    = threadIdx.x;     // 0..127

    const size_t base = (((size_t)(b * 16 + win) * NH) + head) * (LTOK * DH);

    // cooperative K/V tile loads (coalesced float4, 16 each)
    {
        const float4* kg = (const float4*)(g_k + base);
        const float4* vg = (const float4*)(g_v + base);
        float4* ks4 = (float4*)Ks;
        float4* vs4 = (float4*)Vs;
        #pragma unroll
        for (int u = 0; u < 16; u++) {
            ks4[u * 128 + i] = kg[u * 128 + i];
            vs4[u * 128 + i] = vg[u * 128 + i];
        }
    }

    // masks for rows i and i+128: row r -> pixel ((r>>4)*4+sy, (r&15)*4+sx)
    // row i+128 maps to (ha+32, wa).
    const int ha = (i >> 4) * 4 + sy;
    const int wa = (i & 15) * 4 + sx;
    const float mk_a = __ldg(&mask_k[(size_t)b * HW + ha * 64 + wa]);
    const float mk_b = __ldg(&mask_k[(size_t)b * HW + (ha + 32) * 64 + wa]);
    const float mq_a = __ldg(&mask_q[(size_t)b * HW + ha * 64 + wa]);
    const float mq_b = __ldg(&mask_q[(size_t)b * HW + (ha + 32) * 64 + wa]);
    mks[i]       = mk_a;
    mks[i + 128] = mk_b;

    // any unmasked key? (exact count not needed; loop skips masked keys)
    const int anyk = __syncthreads_count((mk_a != 0.0f) || (mk_b != 0.0f));

    // Q rows -> packed pairs, pre-scaled by head_dim^-0.5
    const float scaling = 0.17677669529663687f;  // 32^-0.5
    const ull sc2 = pack2(scaling, scaling);
    ull qa[DH / 2], qb[DH / 2];
    {
        const ulonglong2* qga = (const ulonglong2*)(g_q + base + (size_t)i * DH);
        const ulonglong2* qgb = (const ulonglong2*)(g_q + base + (size_t)(i + 128) * DH);
        #pragma unroll
        for (int u = 0; u < 8; u++) {
            ulonglong2 xa = qga[u];
            ulonglong2 xb = qgb[u];
            qa[2 * u + 0] = mul2(xa.x, sc2);
            qa[2 * u + 1] = mul2(xa.y, sc2);
            qb[2 * u + 0] = mul2(xb.x, sc2);
            qb[2 * u + 1] = mul2(xb.y, sc2);
        }
    }

    ull oa[DH / 2], ob[DH / 2];
    #pragma unroll
    for (int d = 0; d < DH / 2; d++) { oa[d] = 0ull; ob[d] = 0ull; }
    float da = 0.0f, db = 0.0f;

    for (int j = 0; j < LTOK; j++) {
        if (mks[j] == 0.0f) continue;   // uniform across block: no divergence

        const ulonglong2* kj = (const ulonglong2*)(Ks + j * DH);
        ull sa0 = 0ull, sa1 = 0ull, sb0 = 0ull, sb1 = 0ull;
        #pragma unroll
        for (int u = 0; u < 8; u++) {
            const ulonglong2 kv = kj[u];
            sa0 = fma2(qa[2 * u + 0], kv.x, sa0);
            sa1 = fma2(qa[2 * u + 1], kv.y, sa1);
            sb0 = fma2(qb[2 * u + 0], kv.x, sb0);
            sb1 = fma2(qb[2 * u + 1], kv.y, sb1);
        }
        const float2 a0 = unpack2(sa0), a1 = unpack2(sa1);
        const float2 b0 = unpack2(sb0), b1 = unpack2(sb1);
        const float pa = __expf((a0.x + a0.y) + (a1.x + a1.y));
        const float pb = __expf((b0.x + b0.y) + (b1.x + b1.y));
        da += pa;
        db += pb;

        const ull pa2 = pack2(pa, pa);
        const ull pb2 = pack2(pb, pb);
        const ulonglong2* vj = (const ulonglong2*)(Vs + j * DH);
        #pragma unroll
        for (int u = 0; u < 8; u++) {
            const ulonglong2 vv = vj[u];
            oa[2 * u + 0] = fma2(pa2, vv.x, oa[2 * u + 0]);
            oa[2 * u + 1] = fma2(pa2, vv.y, oa[2 * u + 1]);
            ob[2 * u + 0] = fma2(pb2, vv.x, ob[2 * u + 0]);
            ob[2 * u + 1] = fma2(pb2, vv.y, ob[2 * u + 1]);
        }
    }

    const float inva = ((mq_a != 0.0f) && (anyk > 0)) ? (1.0f / da) : 0.0f;
    const float invb = ((mq_b != 0.0f) && (anyk > 0)) ? (1.0f / db) : 0.0f;

    // de-window stores: out[b, head*32+dh, h, w];  row i+128 -> (ha+32, wa)
    float* opa = out + ((size_t)b * 256 + head * 32) * HW + (size_t)ha * 64 + wa;
    float* opb = opa + (size_t)32 * 64;
    #pragma unroll
    for (int d = 0; d < DH / 2; d++) {
        const float2 va = unpack2(oa[d]);
        const float2 vb = unpack2(ob[d]);
        opa[(size_t)(2 * d + 0) * HW] = va.x * inva;
        opa[(size_t)(2 * d + 1) * HW] = va.y * inva;
        opb[(size_t)(2 * d + 0) * HW] = vb.x * invb;
        opb[(size_t)(2 * d + 1) * HW] = vb.y * invb;
    }
}

// ---------------------------------------------------------------------------
extern "C" void kernel_launch(void* const* d_in, const int* in_sizes, int n_in,
                              void* d_out, int out_size)
{
    const float* fq     = (const float*)d_in[0];
    const float* fk     = (const float*)d_in[1];
    const float* fv     = (const float*)d_in[2];
    const float* mask_q = (const float*)d_in[3];
    const float* mask_k = (const float*)d_in[4];
    const float* qw     = (const float*)d_in[5];
    const float* qb     = (const float*)d_in[6];
    const float* kw     = (const float*)d_in[7];
    const float* kb     = (const float*)d_in[8];
    const float* vw     = (const float*)d_in[9];
    const float* vb     = (const float*)d_in[10];
    float* out = (float*)d_out;

    const int proj_smem = (2 * 16 * 256 + 2 * 16 * 64) * (int)sizeof(float); // 40960
    cudaFuncSetAttribute(proj_kernel,
                         cudaFuncAttributeMaxDynamicSharedMemorySize, proj_smem);
    proj_kernel<<<dim3(64, 2, 12), 256, proj_smem>>>(
        fq, fk, fv, qw, qb, kw, kb, vw, vb);

    const int attn_smem = (2 * LTOK * DH + LTOK) * (int)sizeof(float);  // 66560
    cudaFuncSetAttribute(attn_kernel,
                         cudaFuncAttributeMaxDynamicSharedMemorySize, attn_smem);
    attn_kernel<<<dim3(NH, 16, 4), 128, attn_smem>>>(mask_q, mask_k, out);
}